// round 3
// baseline (speedup 1.0000x reference)
#include <cuda_runtime.h>
#include <math.h>

// Problem constants (shapes are fixed by the dataset).
#define NMAX 100000
#define DF   128

// Scratch: __device__ globals (allocation is forbidden; this is the sanctioned path).
__device__ float g_agg1[(size_t)NMAX * DF];   // 51.2 MB: edge-sum then nb1
__device__ float g_agg2[(size_t)NMAX * DF];   // 51.2 MB: edge-sum of nb1 (nb2*deg)
__device__ float g_Wc[DF * 384];              // combined weights [j][k], K = 384
__device__ int   g_idx64;                     // 1 if edge indices are int64, else 0

// ---------------------------------------------------------------------------
// Detect edge-index dtype. For int64 (little-endian) values < 2^31 every odd
// 32-bit word is 0; for random int32 in [0, 100000) that is ~impossible.
// ---------------------------------------------------------------------------
__global__ void detect_idx_kernel(const unsigned int* __restrict__ ei_raw) {
    if (threadIdx.x == 0 && blockIdx.x == 0) {
        unsigned int acc = 0;
#pragma unroll
        for (int i = 0; i < 64; i++) acc |= ei_raw[2 * i + 1];
        g_idx64 = (acc == 0u) ? 1 : 0;
    }
}

// ---------------------------------------------------------------------------
// Zero a float4 array
// ---------------------------------------------------------------------------
__global__ void zero4_kernel(float4* __restrict__ p, int n4) {
    int i = blockIdx.x * blockDim.x + threadIdx.x;
    if (i < n4) p[i] = make_float4(0.f, 0.f, 0.f, 0.f);
}

// ---------------------------------------------------------------------------
// Edge scatter-add: acc[dst] += x[src], one warp per edge, one float4 per lane.
// Uses vector red.global.add.v4.f32 (sm_90+) -> 4x fewer L2 atomic ops.
// ---------------------------------------------------------------------------
__global__ void edge_scatter_kernel(const int* __restrict__ ei32,
                                    const float* __restrict__ x,
                                    float* __restrict__ acc,
                                    long long E) {
    long long gid = (long long)blockIdx.x * blockDim.x + threadIdx.x;
    long long e = gid >> 5;
    if (e >= E) return;
    int c = (int)(gid & 31);
    int src, dst;
    if (g_idx64) {
        src = ei32[2 * e];             // low word of int64 (values < 2^31)
        dst = ei32[2 * (e + E)];
    } else {
        src = ei32[e];
        dst = ei32[e + E];
    }
    float4 v = ((const float4*)x)[(long long)src * 32 + c];
    float* p = acc + (long long)dst * DF + c * 4;
    asm volatile("red.global.add.v4.f32 [%0], {%1,%2,%3,%4};"
                 :: "l"(p), "f"(v.x), "f"(v.y), "f"(v.z), "f"(v.w) : "memory");
}

// ---------------------------------------------------------------------------
// agg1 /= deg (becomes nb1), and zero agg2 for the second pass.
// ---------------------------------------------------------------------------
__global__ void div_and_zero_kernel(float4* __restrict__ agg1,
                                    float4* __restrict__ agg2,
                                    const float* __restrict__ deg, int n4) {
    int i = blockIdx.x * blockDim.x + threadIdx.x;
    if (i >= n4) return;
    float rd = 1.0f / deg[i >> 5];     // 32 float4 per row
    float4 v = agg1[i];
    v.x *= rd; v.y *= rd; v.z *= rd; v.w *= rd;
    agg1[i] = v;
    agg2[i] = make_float4(0.f, 0.f, 0.f, 0.f);
}

// ---------------------------------------------------------------------------
// Combine 4 weight matrices into one [128][384] matrix:
//   z = h @ A^T + nb1 @ B^T + nb2 @ C^T + bias
//   A = s0*W_self + s2*W_hp ; B = s1*W_nb1 - s2*W_hp ; C = s3*W_nb2
// ---------------------------------------------------------------------------
__global__ void weight_combine_kernel(const float* __restrict__ Wself,
                                      const float* __restrict__ Wnb1,
                                      const float* __restrict__ Whp,
                                      const float* __restrict__ Wnb2,
                                      const float* __restrict__ logits,
                                      float* __restrict__ Wc) {
    __shared__ float s[4];
    if (threadIdx.x < 4) s[threadIdx.x] = 2.0f / (1.0f + expf(-logits[threadIdx.x]));
    __syncthreads();
    for (int idx = blockIdx.x * blockDim.x + threadIdx.x; idx < DF * DF;
         idx += gridDim.x * blockDim.x) {
        int j = idx >> 7, k = idx & 127;
        Wc[j * 384 + k]       = s[0] * Wself[idx] + s[2] * Whp[idx];
        Wc[j * 384 + 128 + k] = s[1] * Wnb1[idx]  - s[2] * Whp[idx];
        Wc[j * 384 + 256 + k] = s[3] * Wnb2[idx];
    }
}

// ---------------------------------------------------------------------------
// Fused GEMM (M=N nodes, N=128, K=384) + bias + LayerNorm.
// Tile 64x128, 256 threads, per-thread 4x8 register tile, BK=32 smem staging.
// agg2 is scaled by 1/deg on load (nb2). LN done in-block via smem + shfl.
// ---------------------------------------------------------------------------
__global__ __launch_bounds__(256) void fused_gemm_ln_kernel(
    const float* __restrict__ h, const float* __restrict__ agg1,
    const float* __restrict__ agg2, const float* __restrict__ deg,
    const float* __restrict__ Wc, const float* __restrict__ bias,
    const float* __restrict__ gamma, const float* __restrict__ beta,
    float* __restrict__ out, int Nn) {
    constexpr int BM = 64, BN = 128, BK = 32;
    __shared__ union SU {
        struct { float Xs[BK][BM + 4]; float Ws[BK][BN + 4]; } s;
        float Zs[BM][BN + 4];
    } u;
    __shared__ float rdeg_s[BM];

    int tid = threadIdx.x;
    int row0 = blockIdx.x * BM;
    if (tid < BM) {
        int r = row0 + tid;
        rdeg_s[tid] = (r < Nn) ? (1.0f / deg[r]) : 0.0f;
    }
    __syncthreads();

    float acc[4][8];
#pragma unroll
    for (int i = 0; i < 4; i++)
#pragma unroll
        for (int j = 0; j < 8; j++) acc[i][j] = 0.f;

    int tx = tid & 15, ty = tid >> 4;   // thread tile coords
    const float* srcs[3] = {h, agg1, agg2};

#pragma unroll 1
    for (int kc = 0; kc < 384; kc += BK) {
        int si = kc >> 7;        // which source array
        int col = kc & 127;      // column offset within source
        const float* S = srcs[si];
        int c = tid & 7, r = tid >> 3;   // loader coords: c = float4 col, r = row
        // X tile: 64 rows x 32 cols (transposed into smem)
#pragma unroll
        for (int rep = 0; rep < 2; rep++) {
            int rr = r + rep * 32;
            int gr = row0 + rr;
            float4 v = make_float4(0.f, 0.f, 0.f, 0.f);
            if (gr < Nn) v = *(const float4*)(S + (long long)gr * DF + col + c * 4);
            if (si == 2) { float rd = rdeg_s[rr]; v.x *= rd; v.y *= rd; v.z *= rd; v.w *= rd; }
            u.s.Xs[c * 4 + 0][rr] = v.x; u.s.Xs[c * 4 + 1][rr] = v.y;
            u.s.Xs[c * 4 + 2][rr] = v.z; u.s.Xs[c * 4 + 3][rr] = v.w;
        }
        // W tile: 128 rows x 32 cols (transposed into smem)
#pragma unroll
        for (int rep = 0; rep < 4; rep++) {
            int rr = r + rep * 32;
            float4 v = *(const float4*)(Wc + rr * 384 + kc + c * 4);
            u.s.Ws[c * 4 + 0][rr] = v.x; u.s.Ws[c * 4 + 1][rr] = v.y;
            u.s.Ws[c * 4 + 2][rr] = v.z; u.s.Ws[c * 4 + 3][rr] = v.w;
        }
        __syncthreads();
#pragma unroll
        for (int kk = 0; kk < BK; kk++) {
            float4 xv = *(const float4*)&u.s.Xs[kk][ty * 4];
            float4 w0 = *(const float4*)&u.s.Ws[kk][tx * 8];
            float4 w1 = *(const float4*)&u.s.Ws[kk][tx * 8 + 4];
            float xr[4] = {xv.x, xv.y, xv.z, xv.w};
            float wr[8] = {w0.x, w0.y, w0.z, w0.w, w1.x, w1.y, w1.z, w1.w};
#pragma unroll
            for (int i = 0; i < 4; i++)
#pragma unroll
                for (int j = 0; j < 8; j++)
                    acc[i][j] = fmaf(xr[i], wr[j], acc[i][j]);
        }
        __syncthreads();
    }

    // Epilogue: z -> smem (with bias), then per-row LayerNorm.
    float4 b0 = *(const float4*)(bias + tx * 8);
    float4 b1 = *(const float4*)(bias + tx * 8 + 4);
    float br[8] = {b0.x, b0.y, b0.z, b0.w, b1.x, b1.y, b1.z, b1.w};
#pragma unroll
    for (int i = 0; i < 4; i++)
#pragma unroll
        for (int j = 0; j < 8; j++)
            u.Zs[ty * 4 + i][tx * 8 + j] = acc[i][j] + br[j];
    __syncthreads();

    int warp = tid >> 5, lane = tid & 31;
    float4 g4 = *(const float4*)(gamma + lane * 4);
    float4 be4 = *(const float4*)(beta + lane * 4);
#pragma unroll 1
    for (int rr = 0; rr < 8; rr++) {
        int r = warp * 8 + rr;
        float4 v = *(const float4*)&u.Zs[r][lane * 4];
        float s = v.x + v.y + v.z + v.w;
        float q = v.x * v.x + v.y * v.y + v.z * v.z + v.w * v.w;
#pragma unroll
        for (int o = 16; o > 0; o >>= 1) {
            s += __shfl_xor_sync(0xffffffffu, s, o);
            q += __shfl_xor_sync(0xffffffffu, q, o);
        }
        float mean = s * (1.0f / 128.0f);
        float var  = q * (1.0f / 128.0f) - mean * mean;
        float inv  = rsqrtf(var + 1e-5f);
        int gr = row0 + r;
        if (gr < Nn) {
            float4 o4;
            o4.x = (v.x - mean) * inv * g4.x + be4.x;
            o4.y = (v.y - mean) * inv * g4.y + be4.y;
            o4.z = (v.z - mean) * inv * g4.z + be4.z;
            o4.w = (v.w - mean) * inv * g4.w + be4.w;
            *(float4*)(out + (long long)gr * DF + lane * 4) = o4;
        }
    }
}

// ---------------------------------------------------------------------------
// Launch
// ---------------------------------------------------------------------------
extern "C" void kernel_launch(void* const* d_in, const int* in_sizes, int n_in,
                              void* d_out, int out_size) {
    const float* h      = (const float*)d_in[0];
    const int*   ei32   = (const int*)d_in[1];    // int32 OR int64 (auto-detected)
    const float* deg    = (const float*)d_in[2];
    const float* Wself  = (const float*)d_in[3];
    const float* Wnb1   = (const float*)d_in[4];
    const float* Whp    = (const float*)d_in[5];
    const float* Wnb2   = (const float*)d_in[6];
    const float* bias   = (const float*)d_in[7];
    const float* logits = (const float*)d_in[8];
    const float* gamma  = (const float*)d_in[9];
    const float* beta   = (const float*)d_in[10];
    float*       out    = (float*)d_out;

    int Nn = in_sizes[2];                 // deg has N elements
    long long E = in_sizes[1] / 2;        // edge_index is (2, E)
    int n4 = Nn * (DF / 4);               // float4 count per agg array

    float *agg1, *agg2, *Wc;
    cudaGetSymbolAddress((void**)&agg1, g_agg1);
    cudaGetSymbolAddress((void**)&agg2, g_agg2);
    cudaGetSymbolAddress((void**)&Wc,   g_Wc);

    const int T = 256;
    int zb = (n4 + T - 1) / T;
    long long etot = E * 32;
    int eb = (int)((etot + T - 1) / T);
    int fb = (Nn + 63) / 64;

    // 0) detect index dtype (int32 vs int64)
    detect_idx_kernel<<<1, 32>>>((const unsigned int*)ei32);
    // 1) agg1 = 0
    zero4_kernel<<<zb, T>>>((float4*)agg1, n4);
    // 2) agg1[dst] += h[src]
    edge_scatter_kernel<<<eb, T>>>(ei32, h, agg1, E);
    // 3) agg1 /= deg (-> nb1); agg2 = 0
    div_and_zero_kernel<<<zb, T>>>((float4*)agg1, (float4*)agg2, deg, n4);
    // 4) agg2[dst] += nb1[src]
    edge_scatter_kernel<<<eb, T>>>(ei32, agg1, agg2, E);
    // 5) combined weights (scales via sigmoid on device)
    weight_combine_kernel<<<64, T>>>(Wself, Wnb1, Whp, Wnb2, logits, Wc);
    // 6) fused GEMM (K=384) + bias + LayerNorm
    fused_gemm_ln_kernel<<<fb, T>>>(h, agg1, agg2, deg, Wc, bias, gamma, beta, out, Nn);
}

// round 4
// speedup vs baseline: 2.2707x; 2.2707x over previous
#include <cuda_runtime.h>
#include <math.h>

#define NMAX 100000
#define EMAX 1600000
#define DF   128
#define SCAN_B 1024

// Scratch (__device__ globals; allocation is forbidden).
__device__ float g_agg1[(size_t)NMAX * DF];   // nb1 (mean applied)
__device__ float g_agg2[(size_t)NMAX * DF];   // nb2 (mean applied)
__device__ float g_Wc[DF * 384];              // combined weights
__device__ int   g_idx64;                     // 1 if edge indices are int64
__device__ int   g_cnt[NMAX];                 // histogram / fill cursor
__device__ int   g_scan[NMAX];                // per-block inclusive scan
__device__ int   g_bsum[1024];                // block sums -> exclusive offsets
__device__ int   g_rowptr[NMAX + 1];          // CSR row pointer (by dst)
__device__ int   g_esrc[EMAX];                // CSR adjacency: src per edge

// ---------------------------------------------------------------------------
// Detect edge-index dtype (int64 little-endian has zero odd words for v<2^31).
// ---------------------------------------------------------------------------
__global__ void detect_idx_kernel(const unsigned int* __restrict__ ei_raw) {
    if (threadIdx.x == 0 && blockIdx.x == 0) {
        unsigned int acc = 0;
#pragma unroll
        for (int i = 0; i < 64; i++) acc |= ei_raw[2 * i + 1];
        g_idx64 = (acc == 0u) ? 1 : 0;
    }
}

__device__ __forceinline__ int load_idx(const int* __restrict__ ei32,
                                        long long pos, int idx64) {
    return idx64 ? ei32[2 * pos] : ei32[pos];
}

// ---------------------------------------------------------------------------
// CSR build: zero counts -> histogram(dst) -> scan -> fill
// ---------------------------------------------------------------------------
__global__ void cnt_zero_kernel(int* __restrict__ cnt, int n) {
    int i = blockIdx.x * blockDim.x + threadIdx.x;
    if (i < n) cnt[i] = 0;
}

__global__ void hist_kernel(const int* __restrict__ ei32, int* __restrict__ cnt,
                            long long E) {
    long long e = (long long)blockIdx.x * blockDim.x + threadIdx.x;
    if (e >= E) return;
    int dst = load_idx(ei32, e + E, g_idx64);
    atomicAdd(&cnt[dst], 1);
}

__global__ void scan_a_kernel(const int* __restrict__ cnt, int* __restrict__ scan,
                              int* __restrict__ bsum, int n) {
    __shared__ int sh[SCAN_B];
    int tid = threadIdx.x;
    int i = blockIdx.x * SCAN_B + tid;
    sh[tid] = (i < n) ? cnt[i] : 0;
    __syncthreads();
#pragma unroll
    for (int o = 1; o < SCAN_B; o <<= 1) {
        int t = (tid >= o) ? sh[tid - o] : 0;
        __syncthreads();
        if (tid >= o) sh[tid] += t;
        __syncthreads();
    }
    if (i < n) scan[i] = sh[tid];
    if (tid == SCAN_B - 1) bsum[blockIdx.x] = sh[tid];
}

__global__ void scan_b_kernel(int* __restrict__ bsum, int nb) {
    __shared__ int sh[1024];
    int tid = threadIdx.x;
    int v = (tid < nb) ? bsum[tid] : 0;
    sh[tid] = v;
    __syncthreads();
#pragma unroll
    for (int o = 1; o < 1024; o <<= 1) {
        int t = (tid >= o) ? sh[tid - o] : 0;
        __syncthreads();
        if (tid >= o) sh[tid] += t;
        __syncthreads();
    }
    if (tid < nb) bsum[tid] = sh[tid] - v;   // exclusive
}

__global__ void scan_c_kernel(const int* __restrict__ scan,
                              const int* __restrict__ bsum,
                              int* __restrict__ rowptr, int* __restrict__ cnt, int n) {
    int i = blockIdx.x * blockDim.x + threadIdx.x;
    if (i < n) {
        rowptr[i + 1] = scan[i] + bsum[i / SCAN_B];
        cnt[i] = 0;                          // becomes fill cursor
    }
    if (i == 0) rowptr[0] = 0;
}

__global__ void fill_kernel(const int* __restrict__ ei32,
                            const int* __restrict__ rowptr,
                            int* __restrict__ cur, int* __restrict__ esrc,
                            long long E) {
    long long e = (long long)blockIdx.x * blockDim.x + threadIdx.x;
    if (e >= E) return;
    int idx64 = g_idx64;
    int src = load_idx(ei32, e, idx64);
    int dst = load_idx(ei32, e + E, idx64);
    int pos = atomicAdd(&cur[dst], 1);
    esrc[rowptr[dst] + pos] = src;
}

// ---------------------------------------------------------------------------
// Gather-based mean aggregation: warp per node, lane owns one float4 (4 dims).
// out[node] = (sum over incoming src of x[src]) / deg[node]
// ---------------------------------------------------------------------------
__global__ __launch_bounds__(256) void agg_gather_kernel(
    const int* __restrict__ rowptr, const int* __restrict__ esrc,
    const float4* __restrict__ x4, float4* __restrict__ out4,
    const float* __restrict__ deg, int Nn) {
    int w = (blockIdx.x * blockDim.x + threadIdx.x) >> 5;
    if (w >= Nn) return;
    int lane = threadIdx.x & 31;
    int s = rowptr[w], t = rowptr[w + 1];
    float4 a = make_float4(0.f, 0.f, 0.f, 0.f);
    int j = s;
    for (; j + 4 <= t; j += 4) {
        int s0 = esrc[j], s1 = esrc[j + 1], s2 = esrc[j + 2], s3 = esrc[j + 3];
        float4 v0 = x4[(long long)s0 * 32 + lane];
        float4 v1 = x4[(long long)s1 * 32 + lane];
        float4 v2 = x4[(long long)s2 * 32 + lane];
        float4 v3 = x4[(long long)s3 * 32 + lane];
        a.x += (v0.x + v1.x) + (v2.x + v3.x);
        a.y += (v0.y + v1.y) + (v2.y + v3.y);
        a.z += (v0.z + v1.z) + (v2.z + v3.z);
        a.w += (v0.w + v1.w) + (v2.w + v3.w);
    }
    for (; j < t; j++) {
        int s0 = esrc[j];
        float4 v = x4[(long long)s0 * 32 + lane];
        a.x += v.x; a.y += v.y; a.z += v.z; a.w += v.w;
    }
    float rd = 1.0f / deg[w];
    a.x *= rd; a.y *= rd; a.z *= rd; a.w *= rd;
    out4[(long long)w * 32 + lane] = a;
}

// ---------------------------------------------------------------------------
// Combine 4 weight matrices into one [128][384] matrix.
// ---------------------------------------------------------------------------
__global__ void weight_combine_kernel(const float* __restrict__ Wself,
                                      const float* __restrict__ Wnb1,
                                      const float* __restrict__ Whp,
                                      const float* __restrict__ Wnb2,
                                      const float* __restrict__ logits,
                                      float* __restrict__ Wc) {
    __shared__ float s[4];
    if (threadIdx.x < 4) s[threadIdx.x] = 2.0f / (1.0f + expf(-logits[threadIdx.x]));
    __syncthreads();
    for (int idx = blockIdx.x * blockDim.x + threadIdx.x; idx < DF * DF;
         idx += gridDim.x * blockDim.x) {
        int j = idx >> 7, k = idx & 127;
        Wc[j * 384 + k]       = s[0] * Wself[idx] + s[2] * Whp[idx];
        Wc[j * 384 + 128 + k] = s[1] * Wnb1[idx]  - s[2] * Whp[idx];
        Wc[j * 384 + 256 + k] = s[3] * Wnb2[idx];
    }
}

// ---------------------------------------------------------------------------
// Fused GEMM (M=Nn, N=128, K=384) + bias + LayerNorm.
// ---------------------------------------------------------------------------
__global__ __launch_bounds__(256) void fused_gemm_ln_kernel(
    const float* __restrict__ h, const float* __restrict__ nb1,
    const float* __restrict__ nb2,
    const float* __restrict__ Wc, const float* __restrict__ bias,
    const float* __restrict__ gamma, const float* __restrict__ beta,
    float* __restrict__ out, int Nn) {
    constexpr int BM = 64, BN = 128, BK = 32;
    __shared__ union SU {
        struct { float Xs[BK][BM + 4]; float Ws[BK][BN + 4]; } s;
        float Zs[BM][BN + 4];
    } u;

    int tid = threadIdx.x;
    int row0 = blockIdx.x * BM;

    float acc[4][8];
#pragma unroll
    for (int i = 0; i < 4; i++)
#pragma unroll
        for (int j = 0; j < 8; j++) acc[i][j] = 0.f;

    int tx = tid & 15, ty = tid >> 4;
    const float* srcs[3] = {h, nb1, nb2};

#pragma unroll 1
    for (int kc = 0; kc < 384; kc += BK) {
        int si = kc >> 7;
        int col = kc & 127;
        const float* S = srcs[si];
        int c = tid & 7, r = tid >> 3;
#pragma unroll
        for (int rep = 0; rep < 2; rep++) {
            int rr = r + rep * 32;
            int gr = row0 + rr;
            float4 v = make_float4(0.f, 0.f, 0.f, 0.f);
            if (gr < Nn) v = *(const float4*)(S + (long long)gr * DF + col + c * 4);
            u.s.Xs[c * 4 + 0][rr] = v.x; u.s.Xs[c * 4 + 1][rr] = v.y;
            u.s.Xs[c * 4 + 2][rr] = v.z; u.s.Xs[c * 4 + 3][rr] = v.w;
        }
#pragma unroll
        for (int rep = 0; rep < 4; rep++) {
            int rr = r + rep * 32;
            float4 v = *(const float4*)(Wc + rr * 384 + kc + c * 4);
            u.s.Ws[c * 4 + 0][rr] = v.x; u.s.Ws[c * 4 + 1][rr] = v.y;
            u.s.Ws[c * 4 + 2][rr] = v.z; u.s.Ws[c * 4 + 3][rr] = v.w;
        }
        __syncthreads();
#pragma unroll
        for (int kk = 0; kk < BK; kk++) {
            float4 xv = *(const float4*)&u.s.Xs[kk][ty * 4];
            float4 w0 = *(const float4*)&u.s.Ws[kk][tx * 8];
            float4 w1 = *(const float4*)&u.s.Ws[kk][tx * 8 + 4];
            float xr[4] = {xv.x, xv.y, xv.z, xv.w};
            float wr[8] = {w0.x, w0.y, w0.z, w0.w, w1.x, w1.y, w1.z, w1.w};
#pragma unroll
            for (int i = 0; i < 4; i++)
#pragma unroll
                for (int j = 0; j < 8; j++)
                    acc[i][j] = fmaf(xr[i], wr[j], acc[i][j]);
        }
        __syncthreads();
    }

    float4 b0 = *(const float4*)(bias + tx * 8);
    float4 b1 = *(const float4*)(bias + tx * 8 + 4);
    float br[8] = {b0.x, b0.y, b0.z, b0.w, b1.x, b1.y, b1.z, b1.w};
#pragma unroll
    for (int i = 0; i < 4; i++)
#pragma unroll
        for (int j = 0; j < 8; j++)
            u.Zs[ty * 4 + i][tx * 8 + j] = acc[i][j] + br[j];
    __syncthreads();

    int warp = tid >> 5, lane = tid & 31;
    float4 g4 = *(const float4*)(gamma + lane * 4);
    float4 be4 = *(const float4*)(beta + lane * 4);
#pragma unroll 1
    for (int rr = 0; rr < 8; rr++) {
        int r = warp * 8 + rr;
        float4 v = *(const float4*)&u.Zs[r][lane * 4];
        float s = v.x + v.y + v.z + v.w;
        float q = v.x * v.x + v.y * v.y + v.z * v.z + v.w * v.w;
#pragma unroll
        for (int o = 16; o > 0; o >>= 1) {
            s += __shfl_xor_sync(0xffffffffu, s, o);
            q += __shfl_xor_sync(0xffffffffu, q, o);
        }
        float mean = s * (1.0f / 128.0f);
        float var  = q * (1.0f / 128.0f) - mean * mean;
        float inv  = rsqrtf(var + 1e-5f);
        int gr = row0 + r;
        if (gr < Nn) {
            float4 o4;
            o4.x = (v.x - mean) * inv * g4.x + be4.x;
            o4.y = (v.y - mean) * inv * g4.y + be4.y;
            o4.z = (v.z - mean) * inv * g4.z + be4.z;
            o4.w = (v.w - mean) * inv * g4.w + be4.w;
            *(float4*)(out + (long long)gr * DF + lane * 4) = o4;
        }
    }
}

// ---------------------------------------------------------------------------
// Launch
// ---------------------------------------------------------------------------
extern "C" void kernel_launch(void* const* d_in, const int* in_sizes, int n_in,
                              void* d_out, int out_size) {
    const float* h      = (const float*)d_in[0];
    const int*   ei32   = (const int*)d_in[1];    // int32 or int64 (auto-detected)
    const float* deg    = (const float*)d_in[2];
    const float* Wself  = (const float*)d_in[3];
    const float* Wnb1   = (const float*)d_in[4];
    const float* Whp    = (const float*)d_in[5];
    const float* Wnb2   = (const float*)d_in[6];
    const float* bias   = (const float*)d_in[7];
    const float* logits = (const float*)d_in[8];
    const float* gamma  = (const float*)d_in[9];
    const float* beta   = (const float*)d_in[10];
    float*       out    = (float*)d_out;

    int Nn = in_sizes[2];
    long long E = in_sizes[1] / 2;

    float *agg1, *agg2, *Wc;
    int *cnt, *scan, *bsum, *rowptr, *esrc;
    cudaGetSymbolAddress((void**)&agg1,   g_agg1);
    cudaGetSymbolAddress((void**)&agg2,   g_agg2);
    cudaGetSymbolAddress((void**)&Wc,     g_Wc);
    cudaGetSymbolAddress((void**)&cnt,    g_cnt);
    cudaGetSymbolAddress((void**)&scan,   g_scan);
    cudaGetSymbolAddress((void**)&bsum,   g_bsum);
    cudaGetSymbolAddress((void**)&rowptr, g_rowptr);
    cudaGetSymbolAddress((void**)&esrc,   g_esrc);

    const int T = 256;
    int nb_nodes = (Nn + T - 1) / T;
    int nb_edges = (int)((E + T - 1) / T);
    int nb_scan  = (Nn + SCAN_B - 1) / SCAN_B;
    int nb_agg   = (Nn * 32 + T - 1) / T;          // warp per node
    int fb       = (Nn + 63) / 64;

    // 0) dtype detect
    detect_idx_kernel<<<1, 32>>>((const unsigned int*)ei32);
    // 1) CSR build (by dst)
    cnt_zero_kernel<<<nb_nodes, T>>>(cnt, Nn);
    hist_kernel<<<nb_edges, T>>>(ei32, cnt, E);
    scan_a_kernel<<<nb_scan, SCAN_B>>>(cnt, scan, bsum, Nn);
    scan_b_kernel<<<1, 1024>>>(bsum, nb_scan);
    scan_c_kernel<<<nb_nodes, T>>>(scan, bsum, rowptr, cnt, Nn);
    fill_kernel<<<nb_edges, T>>>(ei32, rowptr, cnt, esrc, E);
    // 2) combined weights (independent)
    weight_combine_kernel<<<64, T>>>(Wself, Wnb1, Whp, Wnb2, logits, Wc);
    // 3) nb1 = mean-gather(h); nb2 = mean-gather(nb1)
    agg_gather_kernel<<<nb_agg, T>>>(rowptr, esrc, (const float4*)h,
                                     (float4*)agg1, deg, Nn);
    agg_gather_kernel<<<nb_agg, T>>>(rowptr, esrc, (const float4*)agg1,
                                     (float4*)agg2, deg, Nn);
    // 4) fused GEMM + bias + LayerNorm
    fused_gemm_ln_kernel<<<fb, T>>>(h, agg1, agg2, Wc, bias, gamma, beta, out, Nn);
}